// round 14
// baseline (speedup 1.0000x reference)
#include <cuda_runtime.h>
#include <cstdint>

#define H     128
#define MAX_N 50000
#define MAX_E 800000
#define NPAD  50048
#define NCNT  50176

// ---------------------------------------------------------------------------
// Scratch (device globals: no allocations allowed)
// ---------------------------------------------------------------------------
__device__ float g_agg[NPAD * H];          // Hsum (scatter target)
__device__ float g_Pa[NPAD * H];           // x @ Wa + be1
__device__ float g_Pb[NPAD * H];           // x @ Wb
__device__ float g_R [NPAD * H];           // x @ Wn1_top + bn1
__device__ int   g_cnt[NCNT];              // in-degree histogram
// tf32 weight images, n-major + granule swizzle for ldmatrix (4 chunks x 4096 floats)
__device__ float g_Wa[16384], g_Wb[16384], g_Wc[16384];
__device__ float g_Wn1t[16384], g_Wn2img[16384];
__device__ float g_Wcomb[16384];           // (We2 @ Wn1_bot) image
__device__ float g_vb[H];                  // be2 @ Wn1_bot
__device__ int   g_is64;

// ---------------------------------------------------------------------------
// helpers
// ---------------------------------------------------------------------------
__device__ __forceinline__ uint32_t smem_u32(const void* p) {
    uint32_t a;
    asm("{ .reg .u64 t; cvta.to.shared.u64 t, %1; cvt.u32.u64 %0, t; }" : "=r"(a) : "l"(p));
    return a;
}
__device__ __forceinline__ void cp16(uint32_t dst, const void* src, uint32_t sz) {
    asm volatile("cp.async.ca.shared.global [%0], [%1], 16, %2;"
                 :: "r"(dst), "l"(src), "r"(sz) : "memory");
}
#define CP_COMMIT() asm volatile("cp.async.commit_group;" ::: "memory")
#define CP_WAIT(n)  asm volatile("cp.async.wait_group %0;" :: "n"(n) : "memory")

__device__ __forceinline__ uint32_t cvt_tf32(float v) {
    uint32_t r; asm("cvt.rna.tf32.f32 %0, %1;" : "=r"(r) : "f"(v)); return r;
}
__device__ __forceinline__ void mma8(float* c, const uint32_t* a, const uint32_t* b) {
    asm volatile("mma.sync.aligned.m16n8k8.row.col.f32.tf32.tf32.f32 "
        "{%0,%1,%2,%3},{%4,%5,%6,%7},{%8,%9},{%0,%1,%2,%3};"
        : "+f"(c[0]), "+f"(c[1]), "+f"(c[2]), "+f"(c[3])
        : "r"(a[0]), "r"(a[1]), "r"(a[2]), "r"(a[3]), "r"(b[0]), "r"(b[1]));
}
__device__ __forceinline__ void ldmx4(uint32_t* r, uint32_t addr) {
    asm volatile("ldmatrix.sync.aligned.m8n8.x4.shared.b16 {%0,%1,%2,%3}, [%4];"
        : "=r"(r[0]), "=r"(r[1]), "=r"(r[2]), "=r"(r[3]) : "r"(addr));
}
__device__ __forceinline__ void red4(float* p, float a, float b, float c, float d) {
    asm volatile("red.global.add.v4.f32 [%0], {%1, %2, %3, %4};"
                 :: "l"(p), "f"(a), "f"(b), "f"(c), "f"(d) : "memory");
}
// L2 evict_last access policy (created once per thread; ptxas requires the
// two-step createpolicy + ld.global.L2::cache_hint form for 16B vectors).
__device__ __forceinline__ uint64_t make_evict_last_policy() {
    uint64_t pol;
    asm("createpolicy.fractional.L2::evict_last.b64 %0, 1.0;" : "=l"(pol));
    return pol;
}
__device__ __forceinline__ float4 ldg_el(const float* p, uint64_t pol) {
    float4 v;
    asm volatile("ld.global.L2::cache_hint.v4.f32 {%0,%1,%2,%3}, [%4], %5;"
                 : "=f"(v.x), "=f"(v.y), "=f"(v.z), "=f"(v.w) : "l"(p), "l"(pol));
    return v;
}

// ---------------------------------------------------------------------------
// launch 1: detect idx dtype + zero g_cnt
// ---------------------------------------------------------------------------
__global__ void detect_zero_kernel(const unsigned int* __restrict__ e) {
    int i = blockIdx.x * blockDim.x + threadIdx.x;
    if (i == 0)
        g_is64 = (e[1] == 0u && e[3] == 0u && e[5] == 0u && e[7] == 0u) ? 1 : 0;
    if (i < NCNT / 4) ((int4*)g_cnt)[i] = make_int4(0, 0, 0, 0);
}

// ---------------------------------------------------------------------------
// launch 2 (merged): zero agg + build 5 images + wcomb/vb + hist
// blocks [0,320): images; [320,384): wcomb; [384,384+ceil(E/256)): hist
// every block also zeroes its slice of g_agg.
// image layout: W[row_off + c*32 + kk][n] at uint index
//   c*4096 + n*32 + (((kk>>2)^(n&7))<<2) + (kk&3), tf32(rna) pre-rounded.
// ---------------------------------------------------------------------------
__global__ void setup_kernel(const float* __restrict__ We1, const float* __restrict__ We2,
                             const float* __restrict__ Wn1, const float* __restrict__ Wn2,
                             const float* __restrict__ be2, const void* __restrict__ eidx,
                             int n4, int E) {
    int i = blockIdx.x * blockDim.x + threadIdx.x;
    if (i < n4) ((float4*)g_agg)[i] = make_float4(0.f, 0.f, 0.f, 0.f);
    const int b = blockIdx.x;
    if (b < 320) {
        int which = b >> 6;
        int idx = ((b & 63) << 8) + threadIdx.x;   // 0..16383
        const float* W; int row_off; float* img;
        switch (which) {
            case 0: W = We1; row_off =   0; img = g_Wa;   break;
            case 1: W = We1; row_off = 128; img = g_Wb;   break;
            case 2: W = We1; row_off = 256; img = g_Wc;   break;
            case 3: W = Wn1; row_off =   0; img = g_Wn1t; break;
            default: W = Wn2; row_off =  0; img = g_Wn2img; break;
        }
        int c = idx >> 12, rem = idx & 4095, kk = rem >> 7, n = rem & 127;
        float v = W[(size_t)(row_off + c * 32 + kk) * H + n];
        ((uint32_t*)img)[c * 4096 + n * 32 + (((kk >> 2) ^ (n & 7)) << 2) + (kk & 3)] = cvt_tf32(v);
    } else if (b < 384) {
        int idx = ((b - 320) << 8) + threadIdx.x;  // 0..16383
        int k = idx >> 7, n = idx & 127;
        float s = 0.f;
        for (int j = 0; j < H; j++) s += We2[k * H + j] * Wn1[(size_t)(128 + j) * H + n];
        int c = k >> 5, kk = k & 31;
        ((uint32_t*)g_Wcomb)[c * 4096 + n * 32 + (((kk >> 2) ^ (n & 7)) << 2) + (kk & 3)] = cvt_tf32(s);
        if (idx < H) {
            float sv = 0.f;
            for (int j = 0; j < H; j++) sv += be2[j] * Wn1[(size_t)(128 + j) * H + idx];
            g_vb[idx] = sv;
        }
    } else {
        int e = ((b - 384) << 8) + threadIdx.x;
        if (e < E) {
            int col = g_is64 ? (int)((const long long*)eidx)[(long long)E + e]
                             : ((const int*)eidx)[E + e];
            atomicAdd(&g_cnt[col], 1);
        }
    }
}

// ===========================================================================
// Tile machinery: 128x128 tile, 8 warps (4M x 2N), tf32 mma.sync + ldmatrix
// ===========================================================================
struct TileCtx {
    int lane, g, t, wM, wN, ar, halfA, l7;
    uint32_t khA, khB, aRow0, aRow1, bRow0, bRow1, bRow2, bRow3;
    __device__ __forceinline__ void init(int tid) {
        lane = tid & 31;
        int warp = tid >> 5;
        g = lane >> 2; t = lane & 3;
        wM = warp & 3; wN = warp >> 2;
        ar = tid >> 1; halfA = tid & 1;
        l7 = lane & 7;
        khA = (uint32_t)(lane >> 4);
        khB = (uint32_t)((lane >> 3) & 1);
        aRow0 = (uint32_t)((wM * 32 + ((lane >> 3) & 1) * 8 + l7) * 128);
        aRow1 = aRow0 + 16 * 128;
        uint32_t jo = (uint32_t)(lane >> 4);
        bRow0 = (uint32_t)((wN * 64 + (0 + jo) * 8 + l7) * 128);
        bRow1 = (uint32_t)((wN * 64 + (2 + jo) * 8 + l7) * 128);
        bRow2 = (uint32_t)((wN * 64 + (4 + jo) * 8 + l7) * 128);
        bRow3 = (uint32_t)((wN * 64 + (6 + jo) * 8 + l7) * 128);
    }
};

template<bool DOCVT>
__device__ __forceinline__ void kstep(const TileCtx& cx, float acc[2][8][4],
                                      uint32_t Ab, uint32_t Bb, int ks) {
    uint32_t gA = (uint32_t)(((2 * ks + cx.khA) ^ cx.l7) << 4);
    uint32_t gB = (uint32_t)(((2 * ks + cx.khB) ^ cx.l7) << 4);
    uint32_t a0[4], a1[4];
    ldmx4(a0, Ab + cx.aRow0 + gA);
    ldmx4(a1, Ab + cx.aRow1 + gA);
    if (DOCVT) {
        #pragma unroll
        for (int i = 0; i < 4; i++) {
            a0[i] = cvt_tf32(__uint_as_float(a0[i]));
            a1[i] = cvt_tf32(__uint_as_float(a1[i]));
        }
    }
    uint32_t bf[16];
    ldmx4(bf + 0,  Bb + cx.bRow0 + gB);
    ldmx4(bf + 4,  Bb + cx.bRow1 + gB);
    ldmx4(bf + 8,  Bb + cx.bRow2 + gB);
    ldmx4(bf + 12, Bb + cx.bRow3 + gB);
    #pragma unroll
    for (int jn = 0; jn < 8; jn++) {
        mma8(acc[0][jn], a0, bf + 2 * jn);
        mma8(acc[1][jn], a1, bf + 2 * jn);
    }
}

// ---------------------------------------------------------------------------
// Fused precompute: Pa = x@Wa + be1, Pb = x@Wb, R = x@Wn1t + bn1
// smem floats: A full tile 16384 | B dbuf 2x4096 = 24576 (96KB) -> 2 CTA/SM
// ---------------------------------------------------------------------------
__global__ void __launch_bounds__(256, 2)
precompute_kernel(const float* __restrict__ x, const float* __restrict__ be1,
                  const float* __restrict__ bn1, int M)
{
    extern __shared__ __align__(16) float sm[];
    __shared__ float sB1[128], sBn[128];
    const int tid = threadIdx.x;
    TileCtx cx; cx.init(tid);
    const uint32_t aBufU = smem_u32(sm);
    const uint32_t bBufU = smem_u32(sm + 16384);
    if (tid < 128) { sB1[tid] = be1[tid]; sBn[tid] = bn1[tid]; }

    const int T = (M + 127) >> 7;
    for (int tile = blockIdx.x; tile < T; tile += gridDim.x) {
        const int mbase = tile << 7;
        __syncthreads();

        auto stageA = [&](int c) {
            bool valid = (mbase + cx.ar) < M;
            const float* srcA = x + (size_t)(valid ? (mbase + cx.ar) : 0) * H
                              + (c << 5) + cx.halfA * 16;
            uint32_t dstA = aBufU + (uint32_t)(c * 16384 + cx.ar * 128);
            uint32_t sz = valid ? 16u : 0u;
            #pragma unroll
            for (int i = 0; i < 4; i++) {
                int q = cx.halfA * 4 + i, qs = q ^ (cx.ar & 7);
                cp16(dstA + qs * 16, srcA + i * 4, sz);
            }
        };
        auto stageB = [&](int s) {
            const float* img = ((s >> 2) == 0) ? g_Wa : ((s >> 2) == 1) ? g_Wb : g_Wn1t;
            const float4* srcB = (const float4*)(img + (s & 3) * 4096) + tid;
            uint32_t dstB = bBufU + (uint32_t)((s & 1) * 16384) + (uint32_t)tid * 16;
            #pragma unroll
            for (int i = 0; i < 4; i++) cp16(dstB + i * 4096, srcB + i * 256, 16);
        };

        float acc[2][8][4];
        #pragma unroll
        for (int mt = 0; mt < 2; mt++)
            #pragma unroll
            for (int jn = 0; jn < 8; jn++)
                #pragma unroll
                for (int i = 0; i < 4; i++) acc[mt][jn][i] = 0.f;

        stageA(0); stageB(0); CP_COMMIT();
        stageA(1); stageB(1); CP_COMMIT();

        for (int s = 0; s < 12; s++) {
            if (s < 11) { CP_WAIT(1); } else { CP_WAIT(0); }
            __syncthreads();
            uint32_t Ab = aBufU + (uint32_t)((s & 3) * 16384);
            uint32_t Bb = bBufU + (uint32_t)((s & 1) * 16384);
            #pragma unroll
            for (int ks = 0; ks < 4; ks++) kstep<true>(cx, acc, Ab, Bb, ks);
            __syncthreads();
            int ns = s + 2;
            if (ns < 12) {
                if (ns < 4) stageA(ns);
                stageB(ns);
                CP_COMMIT();
            }
            if ((s & 3) == 3) {
                int pass = s >> 2;
                float* outp = (pass == 0) ? g_Pa : (pass == 1) ? g_Pb : g_R;
                #pragma unroll
                for (int mt = 0; mt < 2; mt++) {
                    const int r0r = cx.wM * 32 + cx.g + mt * 16, r8r = r0r + 8;
                    #pragma unroll
                    for (int jn = 0; jn < 8; jn++) {
                        int col0 = cx.wN * 64 + jn * 8 + 2 * cx.t;
                        float b0 = 0.f, b1 = 0.f;
                        if (pass == 0) { b0 = sB1[col0]; b1 = sB1[col0 + 1]; }
                        if (pass == 2) { b0 = sBn[col0]; b1 = sBn[col0 + 1]; }
                        if (mbase + r0r < M)
                            *(float2*)(outp + (size_t)(mbase + r0r) * H + col0) =
                                make_float2(acc[mt][jn][0] + b0, acc[mt][jn][1] + b1);
                        if (mbase + r8r < M)
                            *(float2*)(outp + (size_t)(mbase + r8r) * H + col0) =
                                make_float2(acc[mt][jn][2] + b0, acc[mt][jn][3] + b1);
                        acc[mt][jn][0] = acc[mt][jn][1] = 0.f;
                        acc[mt][jn][2] = acc[mt][jn][3] = 0.f;
                    }
                }
            }
        }
    }
}

// ---------------------------------------------------------------------------
// Edge kernel (R9 structure + idx prefetch + evict_last gathers):
// Q = eattr@Wc (Wc persistent); hid = relu(Q + Pa[row] + Pb[col]);
// coalesced epilogue via 64-slot SMEM transpose (2 passes x 8 rows/warp);
// full-lane red.v4 into g_agg[col] (Hsum). Next tile's edge indices are
// prefetched barrier-free into a double buffer during the current tile.
// smem floats: A dbuf 8192 (reused as transpose buf) | sW1 16384 = 96KB
// ---------------------------------------------------------------------------
__global__ void __launch_bounds__(256, 2)
edge_kernel(const float* __restrict__ eattr, const void* __restrict__ eidx, int M)
{
    extern __shared__ __align__(16) float sm[];
    float* const sW1 = sm + 8192;
    __shared__ int sRow[2][128], sCol[2][128];

    const int tid = threadIdx.x;
    const int warp = tid >> 5;
    TileCtx cx; cx.init(tid);
    const uint32_t aBufU = smem_u32(sm);
    const uint32_t w1U   = smem_u32(sW1);
    const int is64v = g_is64;
    const int ntiles = (M + 127) >> 7;
    const uint64_t pol = make_evict_last_policy();

    auto load_idx = [&](int t, int b) {
        if (tid < 128) {
            int rI = 0, cI = 0;
            int e = (t << 7) + tid;
            if (t < ntiles && e < M) {
                if (is64v) {
                    const long long* p = (const long long*)eidx;
                    rI = (int)p[e]; cI = (int)p[(long long)M + e];
                } else {
                    const int* p = (const int*)eidx;
                    rI = p[e]; cI = p[M + e];
                }
            }
            sRow[b][tid] = rI; sCol[b][tid] = cI;
        }
    };

    { // persistent Wc image
        const float4* s1 = (const float4*)g_Wc;
        float4* d1 = (float4*)sW1;
        #pragma unroll
        for (int i = 0; i < 16; i++) d1[tid + i * 256] = s1[tid + i * 256];
    }
    load_idx(blockIdx.x, 0);     // first tile's indices
    __syncthreads();

    auto stage = [&](int mbase, int c) {
        bool valid = (mbase + cx.ar) < M;
        const float* srcA = eattr + (size_t)(valid ? (mbase + cx.ar) : 0) * H
                          + (c << 5) + cx.halfA * 16;
        uint32_t dstA = aBufU + (uint32_t)((c & 1) * 16384 + cx.ar * 128);
        uint32_t sz = valid ? 16u : 0u;
        #pragma unroll
        for (int i = 0; i < 4; i++) {
            int q = cx.halfA * 4 + i, qs = q ^ (cx.ar & 7);
            cp16(dstA + qs * 16, srcA + i * 4, sz);
        }
        CP_COMMIT();
    };

    int it = 0;
    for (int tile = blockIdx.x; tile < ntiles; tile += gridDim.x, it ^= 1) {
        const int mbase = tile << 7;

        // prefetch NEXT tile's indices into the other buffer (barrier-free:
        // that buffer is only read after the many barriers below + next iter)
        load_idx(tile + gridDim.x, it ^ 1);

        float acc[2][8][4];
        #pragma unroll
        for (int mt = 0; mt < 2; mt++)
            #pragma unroll
            for (int jn = 0; jn < 8; jn++)
                #pragma unroll
                for (int i = 0; i < 4; i++) acc[mt][jn][i] = 0.f;

        stage(mbase, 0); stage(mbase, 1);
        #pragma unroll
        for (int c = 0; c < 4; c++) {
            if (c < 3) { CP_WAIT(1); } else { CP_WAIT(0); }
            __syncthreads();
            uint32_t Ab = aBufU + (uint32_t)((c & 1) * 16384);
            uint32_t Bb = w1U + (uint32_t)(c * 16384);
            #pragma unroll
            for (int ks = 0; ks < 4; ks++) kstep<true>(cx, acc, Ab, Bb, ks);
            __syncthreads();
            if (c + 2 < 4) stage(mbase, c + 2);
        }

        // ---- epilogue: transpose acc via SMEM, coalesced gather/scatter ----
        // Buffer sm[0..8192) = 64 slots x 128 cols; position p of slot s holds
        // original column p ^ ((s&7)<<2); reading at (lane^(s&7))<<2 yields
        // original columns lane*4..+3, so globals use lane*4.
        #pragma unroll
        for (int mt = 0; mt < 2; mt++) {
            const int slotA = cx.wM * 16 + cx.g;       // rows r0
            const int slotB = slotA + 8;               // rows r0+8
            #pragma unroll
            for (int jn = 0; jn < 8; jn++) {
                int col0 = cx.wN * 64 + jn * 8 + 2 * cx.t;
                int ca = col0 ^ ((slotA & 7) << 2);
                int cb = col0 ^ ((slotB & 7) << 2);
                *(float2*)(sm + slotA * 128 + ca) = make_float2(acc[mt][jn][0], acc[mt][jn][1]);
                *(float2*)(sm + slotB * 128 + cb) = make_float2(acc[mt][jn][2], acc[mt][jn][3]);
            }
            __syncthreads();
            // warp w handles slots w*8 .. w*8+7; one row per instruction
            #pragma unroll
            for (int ss = 0; ss < 8; ss++) {
                const int slot = warp * 8 + ss;
                const int row  = (slot >> 4) * 32 + mt * 16 + (slot & 15);
                const bool valid = (mbase + row) < M;
                const int ridx = sRow[it][row], cidx = sCol[it][row];
                const int lc = cx.lane << 2;
                float4 q = *(const float4*)(sm + slot * 128
                                            + ((cx.lane ^ (slot & 7)) << 2));
                if (valid) {
                    const float4 pa = ldg_el(g_Pa + (size_t)ridx * H + lc, pol);
                    const float4 pb = ldg_el(g_Pb + (size_t)cidx * H + lc, pol);
                    red4(g_agg + (size_t)cidx * H + lc,
                         fmaxf(q.x + pa.x + pb.x, 0.f),
                         fmaxf(q.y + pa.y + pb.y, 0.f),
                         fmaxf(q.z + pa.z + pb.z, 0.f),
                         fmaxf(q.w + pa.w + pb.w, 0.f));
                }
            }
            __syncthreads();
        }
    }
}

// ---------------------------------------------------------------------------
// Node kernel: Q = Hsum@Wcomb; hid = relu(Q + R[m] + cnt[m]*vb);
// out = hid@Wn2 + bn2
// smem floats: A dbuf 8192 | sW1 16384 | sW2 16384 | sHid 16384 = 57344 (224KB)
// ---------------------------------------------------------------------------
__global__ void __launch_bounds__(256, 1)
node_kernel(const float* __restrict__ b2v, float* __restrict__ outp, int M)
{
    extern __shared__ __align__(16) float sm[];
    float* const sW1  = sm + 8192;
    float* const sW2  = sm + 24576;
    float* const sHid = sm + 40960;
    __shared__ float sB2[128], sVb[128];

    const int tid = threadIdx.x;
    TileCtx cx; cx.init(tid);
    const uint32_t aBufU = smem_u32(sm);
    const uint32_t w1U   = smem_u32(sW1);
    const uint32_t w2U   = smem_u32(sW2);
    const uint32_t hidU  = smem_u32(sHid);

    {
        const float4* s1 = (const float4*)g_Wcomb;
        const float4* s2 = (const float4*)g_Wn2img;
        float4* d1 = (float4*)sW1; float4* d2 = (float4*)sW2;
        #pragma unroll
        for (int i = 0; i < 16; i++) { d1[tid + i * 256] = s1[tid + i * 256];
                                       d2[tid + i * 256] = s2[tid + i * 256]; }
    }
    if (tid < 128) { sB2[tid] = b2v[tid]; sVb[tid] = g_vb[tid]; }
    __syncthreads();

    const int ntiles = (M + 127) >> 7;
    for (int tile = blockIdx.x; tile < ntiles; tile += gridDim.x) {
        const int mbase = tile << 7;
        __syncthreads();

        auto stage = [&](int c) {
            bool valid = (mbase + cx.ar) < M;
            const float* srcA = g_agg + (size_t)(valid ? (mbase + cx.ar) : 0) * H
                              + (c << 5) + cx.halfA * 16;
            uint32_t dstA = aBufU + (uint32_t)((c & 1) * 16384 + cx.ar * 128);
            uint32_t sz = valid ? 16u : 0u;
            #pragma unroll
            for (int i = 0; i < 4; i++) {
                int q = cx.halfA * 4 + i, qs = q ^ (cx.ar & 7);
                cp16(dstA + qs * 16, srcA + i * 4, sz);
            }
            CP_COMMIT();
        };

        float acc[2][8][4];
        #pragma unroll
        for (int mt = 0; mt < 2; mt++)
            #pragma unroll
            for (int jn = 0; jn < 8; jn++)
                #pragma unroll
                for (int i = 0; i < 4; i++) acc[mt][jn][i] = 0.f;

        stage(0); stage(1);
        #pragma unroll
        for (int c = 0; c < 4; c++) {
            if (c < 3) { CP_WAIT(1); } else { CP_WAIT(0); }
            __syncthreads();
            uint32_t Ab = aBufU + (uint32_t)((c & 1) * 16384);
            uint32_t Bb = w1U + (uint32_t)(c * 16384);
            #pragma unroll
            for (int ks = 0; ks < 4; ks++) kstep<true>(cx, acc, Ab, Bb, ks);
            __syncthreads();
            if (c + 2 < 4) stage(c + 2);
        }

        // hid = relu(acc + R[m] + cnt[m]*vb) -> sHid (tf32, A layout)
        const int axor = cx.g << 2;
        #pragma unroll
        for (int mt = 0; mt < 2; mt++) {
            const int r0r = cx.wM * 32 + cx.g + mt * 16, r8r = r0r + 8;
            const int ia0 = min(mbase + r0r, M - 1);
            const int ia8 = min(mbase + r8r, M - 1);
            const float d0 = (float)g_cnt[ia0];
            const float d8 = (float)g_cnt[ia8];
            #pragma unroll
            for (int jn = 0; jn < 8; jn++) {
                int col0 = cx.wN * 64 + jn * 8 + 2 * cx.t;
                float2 ra = *(const float2*)(g_R + (size_t)ia0 * H + col0);
                float2 rb = *(const float2*)(g_R + (size_t)ia8 * H + col0);
                float vb0 = sVb[col0], vb1 = sVb[col0 + 1];
                uint32_t u0 = cvt_tf32(fmaxf(acc[mt][jn][0] + ra.x + d0 * vb0, 0.f));
                uint32_t u1 = cvt_tf32(fmaxf(acc[mt][jn][1] + ra.y + d0 * vb1, 0.f));
                uint32_t u2 = cvt_tf32(fmaxf(acc[mt][jn][2] + rb.x + d8 * vb0, 0.f));
                uint32_t u3 = cvt_tf32(fmaxf(acc[mt][jn][3] + rb.y + d8 * vb1, 0.f));
                int slab = col0 >> 5, kk = col0 & 31;
                uint32_t* dst = (uint32_t*)(sHid + slab * 4096);
                *(uint2*)(dst + r0r * 32 + (kk ^ axor)) = make_uint2(u0, u1);
                *(uint2*)(dst + r8r * 32 + (kk ^ axor)) = make_uint2(u2, u3);
                acc[mt][jn][0] = acc[mt][jn][1] = acc[mt][jn][2] = acc[mt][jn][3] = 0.f;
            }
        }
        __syncthreads();

        #pragma unroll
        for (int ks16 = 0; ks16 < 16; ks16++)
            kstep<false>(cx, acc,
                         hidU + (uint32_t)((ks16 >> 2) * 16384),
                         w2U  + (uint32_t)((ks16 >> 2) * 16384), ks16 & 3);

        #pragma unroll
        for (int mt = 0; mt < 2; mt++) {
            const int r0r = cx.wM * 32 + cx.g + mt * 16, r8r = r0r + 8;
            #pragma unroll
            for (int jn = 0; jn < 8; jn++) {
                int col0 = cx.wN * 64 + jn * 8 + 2 * cx.t;
                float b0 = sB2[col0], b1 = sB2[col0 + 1];
                if (mbase + r0r < M)
                    *(float2*)(outp + (size_t)(mbase + r0r) * H + col0) =
                        make_float2(acc[mt][jn][0] + b0, acc[mt][jn][1] + b1);
                if (mbase + r8r < M)
                    *(float2*)(outp + (size_t)(mbase + r8r) * H + col0) =
                        make_float2(acc[mt][jn][2] + b0, acc[mt][jn][3] + b1);
            }
        }
    }
}

// ---------------------------------------------------------------------------
#define DYN_PRE  (24576 * 4)   //  96KB
#define DYN_EDGE (24576 * 4)   //  96KB
#define DYN_NODE (57344 * 4)   // 224KB

extern "C" void kernel_launch(void* const* d_in, const int* in_sizes, int n_in,
                              void* d_out, int out_size) {
    const float* x     = (const float*)d_in[0];
    const void*  eidx  = d_in[1];
    const float* eattr = (const float*)d_in[2];
    const float* We1   = (const float*)d_in[3];
    const float* be1   = (const float*)d_in[4];
    const float* We2   = (const float*)d_in[5];
    const float* be2   = (const float*)d_in[6];
    const float* Wn1   = (const float*)d_in[7];
    const float* bn1   = (const float*)d_in[8];
    const float* Wn2   = (const float*)d_in[9];
    const float* bn2   = (const float*)d_in[10];
    float* out = (float*)d_out;

    const int N = in_sizes[0] / H;
    const int E = in_sizes[1] / 2;

    cudaFuncSetAttribute(precompute_kernel, cudaFuncAttributeMaxDynamicSharedMemorySize, DYN_PRE);
    cudaFuncSetAttribute(edge_kernel,       cudaFuncAttributeMaxDynamicSharedMemorySize, DYN_EDGE);
    cudaFuncSetAttribute(node_kernel,       cudaFuncAttributeMaxDynamicSharedMemorySize, DYN_NODE);

    const int n4 = N * H / 4;
    int sgrid = (n4 + 255) / 256;
    const int need = 384 + (E + 255) / 256;
    if (sgrid < need) sgrid = need;

    // Launch order (4th launch gets the ncu capture -> edge_kernel):
    // 1:detect+zero 2:setup(zero/images/wcomb/hist) 3:precompute 4:edge 5:node
    detect_zero_kernel<<<(NCNT / 4 + 255) / 256, 256>>>((const unsigned int*)eidx);
    setup_kernel<<<sgrid, 256>>>(We1, We2, Wn1, Wn2, be2, eidx, n4, E);
    precompute_kernel<<<304, 256, DYN_PRE>>>(x, be1, bn1, N);
    edge_kernel<<<304, 256, DYN_EDGE>>>(eattr, eidx, E);
    node_kernel<<<152, 256, DYN_NODE>>>(bn2, out, N);
}

// round 15
// speedup vs baseline: 1.0795x; 1.0795x over previous
#include <cuda_runtime.h>
#include <cstdint>

#define H     128
#define MAX_N 50000
#define MAX_E 800000
#define NPAD  50048
#define NCNT  50176

// ---------------------------------------------------------------------------
// Scratch (device globals: no allocations allowed)
// ---------------------------------------------------------------------------
__device__ float g_agg[NPAD * H];          // Hsum (scatter target)
__device__ float g_Pa[NPAD * H];           // x @ Wa + be1
__device__ float g_Pb[NPAD * H];           // x @ Wb
__device__ float g_R [NPAD * H];           // x @ Wn1_top + bn1
__device__ int   g_cnt[NCNT];              // in-degree histogram
// tf32 weight images, n-major + granule swizzle for ldmatrix (4 chunks x 4096 floats)
__device__ float g_Wa[16384], g_Wb[16384], g_Wc[16384];
__device__ float g_Wn1t[16384], g_Wn2img[16384];
__device__ float g_Wcomb[16384];           // (We2 @ Wn1_bot) image
__device__ float g_vb[H];                  // be2 @ Wn1_bot
__device__ int   g_is64;

// ---------------------------------------------------------------------------
// helpers
// ---------------------------------------------------------------------------
__device__ __forceinline__ uint32_t smem_u32(const void* p) {
    uint32_t a;
    asm("{ .reg .u64 t; cvta.to.shared.u64 t, %1; cvt.u32.u64 %0, t; }" : "=r"(a) : "l"(p));
    return a;
}
__device__ __forceinline__ void cp16(uint32_t dst, const void* src, uint32_t sz) {
    asm volatile("cp.async.ca.shared.global [%0], [%1], 16, %2;"
                 :: "r"(dst), "l"(src), "r"(sz) : "memory");
}
// cp.async with L2 cache policy (evict_first for streaming eattr)
__device__ __forceinline__ void cp16h(uint32_t dst, const void* src, uint32_t sz, uint64_t pol) {
    asm volatile("cp.async.ca.shared.global.L2::cache_hint [%0], [%1], 16, %2, %3;"
                 :: "r"(dst), "l"(src), "r"(sz), "l"(pol) : "memory");
}
#define CP_COMMIT() asm volatile("cp.async.commit_group;" ::: "memory")
#define CP_WAIT(n)  asm volatile("cp.async.wait_group %0;" :: "n"(n) : "memory")

__device__ __forceinline__ uint32_t cvt_tf32(float v) {
    uint32_t r; asm("cvt.rna.tf32.f32 %0, %1;" : "=r"(r) : "f"(v)); return r;
}
__device__ __forceinline__ void mma8(float* c, const uint32_t* a, const uint32_t* b) {
    asm volatile("mma.sync.aligned.m16n8k8.row.col.f32.tf32.tf32.f32 "
        "{%0,%1,%2,%3},{%4,%5,%6,%7},{%8,%9},{%0,%1,%2,%3};"
        : "+f"(c[0]), "+f"(c[1]), "+f"(c[2]), "+f"(c[3])
        : "r"(a[0]), "r"(a[1]), "r"(a[2]), "r"(a[3]), "r"(b[0]), "r"(b[1]));
}
__device__ __forceinline__ void ldmx4(uint32_t* r, uint32_t addr) {
    asm volatile("ldmatrix.sync.aligned.m8n8.x4.shared.b16 {%0,%1,%2,%3}, [%4];"
        : "=r"(r[0]), "=r"(r[1]), "=r"(r[2]), "=r"(r[3]) : "r"(addr));
}
__device__ __forceinline__ void red4(float* p, float a, float b, float c, float d) {
    asm volatile("red.global.add.v4.f32 [%0], {%1, %2, %3, %4};"
                 :: "l"(p), "f"(a), "f"(b), "f"(c), "f"(d) : "memory");
}
// red with L2 evict_last policy (pins the agg RMW working set in L2)
__device__ __forceinline__ void red4h(float* p, float a, float b, float c, float d, uint64_t pol) {
    asm volatile("red.global.L2::cache_hint.add.v4.f32 [%0], {%1, %2, %3, %4}, %5;"
                 :: "l"(p), "f"(a), "f"(b), "f"(c), "f"(d), "l"(pol) : "memory");
}
__device__ __forceinline__ uint64_t policy_evict_last() {
    uint64_t pol;
    asm("createpolicy.fractional.L2::evict_last.b64 %0, 1.0;" : "=l"(pol));
    return pol;
}
__device__ __forceinline__ uint64_t policy_evict_first() {
    uint64_t pol;
    asm("createpolicy.fractional.L2::evict_first.b64 %0, 1.0;" : "=l"(pol));
    return pol;
}
__device__ __forceinline__ float4 ldg_el(const float* p, uint64_t pol) {
    float4 v;
    asm volatile("ld.global.L2::cache_hint.v4.f32 {%0,%1,%2,%3}, [%4], %5;"
                 : "=f"(v.x), "=f"(v.y), "=f"(v.z), "=f"(v.w) : "l"(p), "l"(pol));
    return v;
}

// ---------------------------------------------------------------------------
// launch 1: detect idx dtype + zero g_cnt
// ---------------------------------------------------------------------------
__global__ void detect_zero_kernel(const unsigned int* __restrict__ e) {
    int i = blockIdx.x * blockDim.x + threadIdx.x;
    if (i == 0)
        g_is64 = (e[1] == 0u && e[3] == 0u && e[5] == 0u && e[7] == 0u) ? 1 : 0;
    if (i < NCNT / 4) ((int4*)g_cnt)[i] = make_int4(0, 0, 0, 0);
}

// ---------------------------------------------------------------------------
// launch 2 (merged): zero agg + build 5 images + wcomb/vb + hist
// blocks [0,320): images; [320,384): wcomb; [384,384+ceil(E/256)): hist
// every block also zeroes its slice of g_agg.
// image layout: W[row_off + c*32 + kk][n] at uint index
//   c*4096 + n*32 + (((kk>>2)^(n&7))<<2) + (kk&3), tf32(rna) pre-rounded.
// ---------------------------------------------------------------------------
__global__ void setup_kernel(const float* __restrict__ We1, const float* __restrict__ We2,
                             const float* __restrict__ Wn1, const float* __restrict__ Wn2,
                             const float* __restrict__ be2, const void* __restrict__ eidx,
                             int n4, int E) {
    int i = blockIdx.x * blockDim.x + threadIdx.x;
    if (i < n4) ((float4*)g_agg)[i] = make_float4(0.f, 0.f, 0.f, 0.f);
    const int b = blockIdx.x;
    if (b < 320) {
        int which = b >> 6;
        int idx = ((b & 63) << 8) + threadIdx.x;   // 0..16383
        const float* W; int row_off; float* img;
        switch (which) {
            case 0: W = We1; row_off =   0; img = g_Wa;   break;
            case 1: W = We1; row_off = 128; img = g_Wb;   break;
            case 2: W = We1; row_off = 256; img = g_Wc;   break;
            case 3: W = Wn1; row_off =   0; img = g_Wn1t; break;
            default: W = Wn2; row_off =  0; img = g_Wn2img; break;
        }
        int c = idx >> 12, rem = idx & 4095, kk = rem >> 7, n = rem & 127;
        float v = W[(size_t)(row_off + c * 32 + kk) * H + n];
        ((uint32_t*)img)[c * 4096 + n * 32 + (((kk >> 2) ^ (n & 7)) << 2) + (kk & 3)] = cvt_tf32(v);
    } else if (b < 384) {
        int idx = ((b - 320) << 8) + threadIdx.x;  // 0..16383
        int k = idx >> 7, n = idx & 127;
        float s = 0.f;
        for (int j = 0; j < H; j++) s += We2[k * H + j] * Wn1[(size_t)(128 + j) * H + n];
        int c = k >> 5, kk = k & 31;
        ((uint32_t*)g_Wcomb)[c * 4096 + n * 32 + (((kk >> 2) ^ (n & 7)) << 2) + (kk & 3)] = cvt_tf32(s);
        if (idx < H) {
            float sv = 0.f;
            for (int j = 0; j < H; j++) sv += be2[j] * Wn1[(size_t)(128 + j) * H + idx];
            g_vb[idx] = sv;
        }
    } else {
        int e = ((b - 384) << 8) + threadIdx.x;
        if (e < E) {
            int col = g_is64 ? (int)((const long long*)eidx)[(long long)E + e]
                             : ((const int*)eidx)[E + e];
            atomicAdd(&g_cnt[col], 1);
        }
    }
}

// ===========================================================================
// Tile machinery: 128x128 tile, 8 warps (4M x 2N), tf32 mma.sync + ldmatrix
// ===========================================================================
struct TileCtx {
    int lane, g, t, wM, wN, ar, halfA, l7;
    uint32_t khA, khB, aRow0, aRow1, bRow0, bRow1, bRow2, bRow3;
    __device__ __forceinline__ void init(int tid) {
        lane = tid & 31;
        int warp = tid >> 5;
        g = lane >> 2; t = lane & 3;
        wM = warp & 3; wN = warp >> 2;
        ar = tid >> 1; halfA = tid & 1;
        l7 = lane & 7;
        khA = (uint32_t)(lane >> 4);
        khB = (uint32_t)((lane >> 3) & 1);
        aRow0 = (uint32_t)((wM * 32 + ((lane >> 3) & 1) * 8 + l7) * 128);
        aRow1 = aRow0 + 16 * 128;
        uint32_t jo = (uint32_t)(lane >> 4);
        bRow0 = (uint32_t)((wN * 64 + (0 + jo) * 8 + l7) * 128);
        bRow1 = (uint32_t)((wN * 64 + (2 + jo) * 8 + l7) * 128);
        bRow2 = (uint32_t)((wN * 64 + (4 + jo) * 8 + l7) * 128);
        bRow3 = (uint32_t)((wN * 64 + (6 + jo) * 8 + l7) * 128);
    }
};

template<bool DOCVT>
__device__ __forceinline__ void kstep(const TileCtx& cx, float acc[2][8][4],
                                      uint32_t Ab, uint32_t Bb, int ks) {
    uint32_t gA = (uint32_t)(((2 * ks + cx.khA) ^ cx.l7) << 4);
    uint32_t gB = (uint32_t)(((2 * ks + cx.khB) ^ cx.l7) << 4);
    uint32_t a0[4], a1[4];
    ldmx4(a0, Ab + cx.aRow0 + gA);
    ldmx4(a1, Ab + cx.aRow1 + gA);
    if (DOCVT) {
        #pragma unroll
        for (int i = 0; i < 4; i++) {
            a0[i] = cvt_tf32(__uint_as_float(a0[i]));
            a1[i] = cvt_tf32(__uint_as_float(a1[i]));
        }
    }
    uint32_t bf[16];
    ldmx4(bf + 0,  Bb + cx.bRow0 + gB);
    ldmx4(bf + 4,  Bb + cx.bRow1 + gB);
    ldmx4(bf + 8,  Bb + cx.bRow2 + gB);
    ldmx4(bf + 12, Bb + cx.bRow3 + gB);
    #pragma unroll
    for (int jn = 0; jn < 8; jn++) {
        mma8(acc[0][jn], a0, bf + 2 * jn);
        mma8(acc[1][jn], a1, bf + 2 * jn);
    }
}

// ---------------------------------------------------------------------------
// Fused precompute: Pa = x@Wa + be1, Pb = x@Wb, R = x@Wn1t + bn1
// smem floats: A full tile 16384 | B dbuf 2x4096 = 24576 (96KB) -> 2 CTA/SM
// ---------------------------------------------------------------------------
__global__ void __launch_bounds__(256, 2)
precompute_kernel(const float* __restrict__ x, const float* __restrict__ be1,
                  const float* __restrict__ bn1, int M)
{
    extern __shared__ __align__(16) float sm[];
    __shared__ float sB1[128], sBn[128];
    const int tid = threadIdx.x;
    TileCtx cx; cx.init(tid);
    const uint32_t aBufU = smem_u32(sm);
    const uint32_t bBufU = smem_u32(sm + 16384);
    if (tid < 128) { sB1[tid] = be1[tid]; sBn[tid] = bn1[tid]; }

    const int T = (M + 127) >> 7;
    for (int tile = blockIdx.x; tile < T; tile += gridDim.x) {
        const int mbase = tile << 7;
        __syncthreads();

        auto stageA = [&](int c) {
            bool valid = (mbase + cx.ar) < M;
            const float* srcA = x + (size_t)(valid ? (mbase + cx.ar) : 0) * H
                              + (c << 5) + cx.halfA * 16;
            uint32_t dstA = aBufU + (uint32_t)(c * 16384 + cx.ar * 128);
            uint32_t sz = valid ? 16u : 0u;
            #pragma unroll
            for (int i = 0; i < 4; i++) {
                int q = cx.halfA * 4 + i, qs = q ^ (cx.ar & 7);
                cp16(dstA + qs * 16, srcA + i * 4, sz);
            }
        };
        auto stageB = [&](int s) {
            const float* img = ((s >> 2) == 0) ? g_Wa : ((s >> 2) == 1) ? g_Wb : g_Wn1t;
            const float4* srcB = (const float4*)(img + (s & 3) * 4096) + tid;
            uint32_t dstB = bBufU + (uint32_t)((s & 1) * 16384) + (uint32_t)tid * 16;
            #pragma unroll
            for (int i = 0; i < 4; i++) cp16(dstB + i * 4096, srcB + i * 256, 16);
        };

        float acc[2][8][4];
        #pragma unroll
        for (int mt = 0; mt < 2; mt++)
            #pragma unroll
            for (int jn = 0; jn < 8; jn++)
                #pragma unroll
                for (int i = 0; i < 4; i++) acc[mt][jn][i] = 0.f;

        stageA(0); stageB(0); CP_COMMIT();
        stageA(1); stageB(1); CP_COMMIT();

        for (int s = 0; s < 12; s++) {
            if (s < 11) { CP_WAIT(1); } else { CP_WAIT(0); }
            __syncthreads();
            uint32_t Ab = aBufU + (uint32_t)((s & 3) * 16384);
            uint32_t Bb = bBufU + (uint32_t)((s & 1) * 16384);
            #pragma unroll
            for (int ks = 0; ks < 4; ks++) kstep<true>(cx, acc, Ab, Bb, ks);
            __syncthreads();
            int ns = s + 2;
            if (ns < 12) {
                if (ns < 4) stageA(ns);
                stageB(ns);
                CP_COMMIT();
            }
            if ((s & 3) == 3) {
                int pass = s >> 2;
                float* outp = (pass == 0) ? g_Pa : (pass == 1) ? g_Pb : g_R;
                #pragma unroll
                for (int mt = 0; mt < 2; mt++) {
                    const int r0r = cx.wM * 32 + cx.g + mt * 16, r8r = r0r + 8;
                    #pragma unroll
                    for (int jn = 0; jn < 8; jn++) {
                        int col0 = cx.wN * 64 + jn * 8 + 2 * cx.t;
                        float b0 = 0.f, b1 = 0.f;
                        if (pass == 0) { b0 = sB1[col0]; b1 = sB1[col0 + 1]; }
                        if (pass == 2) { b0 = sBn[col0]; b1 = sBn[col0 + 1]; }
                        if (mbase + r0r < M)
                            *(float2*)(outp + (size_t)(mbase + r0r) * H + col0) =
                                make_float2(acc[mt][jn][0] + b0, acc[mt][jn][1] + b1);
                        if (mbase + r8r < M)
                            *(float2*)(outp + (size_t)(mbase + r8r) * H + col0) =
                                make_float2(acc[mt][jn][2] + b0, acc[mt][jn][3] + b1);
                        acc[mt][jn][0] = acc[mt][jn][1] = 0.f;
                        acc[mt][jn][2] = acc[mt][jn][3] = 0.f;
                    }
                }
            }
        }
    }
}

// ---------------------------------------------------------------------------
// Edge kernel: Q = eattr@Wc (Wc persistent); hid = relu(Q + Pa[row] + Pb[col]);
// coalesced epilogue via 64-slot SMEM transpose (2 passes x 8 rows/warp);
// red.v4 with evict_last (pin agg RMW set); Pa/Pb gathers evict_last;
// eattr staging evict_first (streaming). Idx double-buffer prefetch.
// smem floats: A dbuf 8192 (reused as transpose buf) | sW1 16384 = 96KB
// ---------------------------------------------------------------------------
__global__ void __launch_bounds__(256, 2)
edge_kernel(const float* __restrict__ eattr, const void* __restrict__ eidx, int M)
{
    extern __shared__ __align__(16) float sm[];
    float* const sW1 = sm + 8192;
    __shared__ int sRow[2][128], sCol[2][128];

    const int tid = threadIdx.x;
    const int warp = tid >> 5;
    TileCtx cx; cx.init(tid);
    const uint32_t aBufU = smem_u32(sm);
    const uint32_t w1U   = smem_u32(sW1);
    const int is64v = g_is64;
    const int ntiles = (M + 127) >> 7;
    const uint64_t polL = policy_evict_last();
    const uint64_t polF = policy_evict_first();

    auto load_idx = [&](int t, int b) {
        if (tid < 128) {
            int rI = 0, cI = 0;
            int e = (t << 7) + tid;
            if (t < ntiles && e < M) {
                if (is64v) {
                    const long long* p = (const long long*)eidx;
                    rI = (int)p[e]; cI = (int)p[(long long)M + e];
                } else {
                    const int* p = (const int*)eidx;
                    rI = p[e]; cI = p[M + e];
                }
            }
            sRow[b][tid] = rI; sCol[b][tid] = cI;
        }
    };

    { // persistent Wc image
        const float4* s1 = (const float4*)g_Wc;
        float4* d1 = (float4*)sW1;
        #pragma unroll
        for (int i = 0; i < 16; i++) d1[tid + i * 256] = s1[tid + i * 256];
    }
    load_idx(blockIdx.x, 0);     // first tile's indices
    __syncthreads();

    auto stage = [&](int mbase, int c) {
        bool valid = (mbase + cx.ar) < M;
        const float* srcA = eattr + (size_t)(valid ? (mbase + cx.ar) : 0) * H
                          + (c << 5) + cx.halfA * 16;
        uint32_t dstA = aBufU + (uint32_t)((c & 1) * 16384 + cx.ar * 128);
        uint32_t sz = valid ? 16u : 0u;
        #pragma unroll
        for (int i = 0; i < 4; i++) {
            int q = cx.halfA * 4 + i, qs = q ^ (cx.ar & 7);
            cp16h(dstA + qs * 16, srcA + i * 4, sz, polF);
        }
        CP_COMMIT();
    };

    int it = 0;
    for (int tile = blockIdx.x; tile < ntiles; tile += gridDim.x, it ^= 1) {
        const int mbase = tile << 7;

        // prefetch NEXT tile's indices into the other buffer (barrier-free:
        // that buffer is only read after the many barriers below + next iter)
        load_idx(tile + gridDim.x, it ^ 1);

        float acc[2][8][4];
        #pragma unroll
        for (int mt = 0; mt < 2; mt++)
            #pragma unroll
            for (int jn = 0; jn < 8; jn++)
                #pragma unroll
                for (int i = 0; i < 4; i++) acc[mt][jn][i] = 0.f;

        stage(mbase, 0); stage(mbase, 1);
        #pragma unroll
        for (int c = 0; c < 4; c++) {
            if (c < 3) { CP_WAIT(1); } else { CP_WAIT(0); }
            __syncthreads();
            uint32_t Ab = aBufU + (uint32_t)((c & 1) * 16384);
            uint32_t Bb = w1U + (uint32_t)(c * 16384);
            #pragma unroll
            for (int ks = 0; ks < 4; ks++) kstep<true>(cx, acc, Ab, Bb, ks);
            __syncthreads();
            if (c + 2 < 4) stage(mbase, c + 2);
        }

        // ---- epilogue: transpose acc via SMEM, coalesced gather/scatter ----
        // Buffer sm[0..8192) = 64 slots x 128 cols; position p of slot s holds
        // original column p ^ ((s&7)<<2); reading at (lane^(s&7))<<2 yields
        // original columns lane*4..+3, so globals use lane*4.
        #pragma unroll
        for (int mt = 0; mt < 2; mt++) {
            const int slotA = cx.wM * 16 + cx.g;       // rows r0
            const int slotB = slotA + 8;               // rows r0+8
            #pragma unroll
            for (int jn = 0; jn < 8; jn++) {
                int col0 = cx.wN * 64 + jn * 8 + 2 * cx.t;
                int ca = col0 ^ ((slotA & 7) << 2);
                int cb = col0 ^ ((slotB & 7) << 2);
                *(float2*)(sm + slotA * 128 + ca) = make_float2(acc[mt][jn][0], acc[mt][jn][1]);
                *(float2*)(sm + slotB * 128 + cb) = make_float2(acc[mt][jn][2], acc[mt][jn][3]);
            }
            __syncthreads();
            // warp w handles slots w*8 .. w*8+7; one row per instruction
            #pragma unroll
            for (int ss = 0; ss < 8; ss++) {
                const int slot = warp * 8 + ss;
                const int row  = (slot >> 4) * 32 + mt * 16 + (slot & 15);
                const bool valid = (mbase + row) < M;
                const int ridx = sRow[it][row], cidx = sCol[it][row];
                const int lc = cx.lane << 2;
                float4 q = *(const float4*)(sm + slot * 128
                                            + ((cx.lane ^ (slot & 7)) << 2));
                if (valid) {
                    const float4 pa = ldg_el(g_Pa + (size_t)ridx * H + lc, polL);
                    const float4 pb = ldg_el(g_Pb + (size_t)cidx * H + lc, polL);
                    red4h(g_agg + (size_t)cidx * H + lc,
                          fmaxf(q.x + pa.x + pb.x, 0.f),
                          fmaxf(q.y + pa.y + pb.y, 0.f),
                          fmaxf(q.z + pa.z + pb.z, 0.f),
                          fmaxf(q.w + pa.w + pb.w, 0.f), polL);
                }
            }
            __syncthreads();
        }
    }
}

// ---------------------------------------------------------------------------
// Node kernel: Q = Hsum@Wcomb; hid = relu(Q + R[m] + cnt[m]*vb);
// out = hid@Wn2 + bn2
// smem floats: A dbuf 8192 | sW1 16384 | sW2 16384 | sHid 16384 = 57344 (224KB)
// ---------------------------------------------------------------------------
__global__ void __launch_bounds__(256, 1)
node_kernel(const float* __restrict__ b2v, float* __restrict__ outp, int M)
{
    extern __shared__ __align__(16) float sm[];
    float* const sW1  = sm + 8192;
    float* const sW2  = sm + 24576;
    float* const sHid = sm + 40960;
    __shared__ float sB2[128], sVb[128];

    const int tid = threadIdx.x;
    TileCtx cx; cx.init(tid);
    const uint32_t aBufU = smem_u32(sm);
    const uint32_t w1U   = smem_u32(sW1);
    const uint32_t w2U   = smem_u32(sW2);
    const uint32_t hidU  = smem_u32(sHid);

    {
        const float4* s1 = (const float4*)g_Wcomb;
        const float4* s2 = (const float4*)g_Wn2img;
        float4* d1 = (float4*)sW1; float4* d2 = (float4*)sW2;
        #pragma unroll
        for (int i = 0; i < 16; i++) { d1[tid + i * 256] = s1[tid + i * 256];
                                       d2[tid + i * 256] = s2[tid + i * 256]; }
    }
    if (tid < 128) { sB2[tid] = b2v[tid]; sVb[tid] = g_vb[tid]; }
    __syncthreads();

    const int ntiles = (M + 127) >> 7;
    for (int tile = blockIdx.x; tile < ntiles; tile += gridDim.x) {
        const int mbase = tile << 7;
        __syncthreads();

        auto stage = [&](int c) {
            bool valid = (mbase + cx.ar) < M;
            const float* srcA = g_agg + (size_t)(valid ? (mbase + cx.ar) : 0) * H
                              + (c << 5) + cx.halfA * 16;
            uint32_t dstA = aBufU + (uint32_t)((c & 1) * 16384 + cx.ar * 128);
            uint32_t sz = valid ? 16u : 0u;
            #pragma unroll
            for (int i = 0; i < 4; i++) {
                int q = cx.halfA * 4 + i, qs = q ^ (cx.ar & 7);
                cp16(dstA + qs * 16, srcA + i * 4, sz);
            }
            CP_COMMIT();
        };

        float acc[2][8][4];
        #pragma unroll
        for (int mt = 0; mt < 2; mt++)
            #pragma unroll
            for (int jn = 0; jn < 8; jn++)
                #pragma unroll
                for (int i = 0; i < 4; i++) acc[mt][jn][i] = 0.f;

        stage(0); stage(1);
        #pragma unroll
        for (int c = 0; c < 4; c++) {
            if (c < 3) { CP_WAIT(1); } else { CP_WAIT(0); }
            __syncthreads();
            uint32_t Ab = aBufU + (uint32_t)((c & 1) * 16384);
            uint32_t Bb = w1U + (uint32_t)(c * 16384);
            #pragma unroll
            for (int ks = 0; ks < 4; ks++) kstep<true>(cx, acc, Ab, Bb, ks);
            __syncthreads();
            if (c + 2 < 4) stage(c + 2);
        }

        // hid = relu(acc + R[m] + cnt[m]*vb) -> sHid (tf32, A layout)
        const int axor = cx.g << 2;
        #pragma unroll
        for (int mt = 0; mt < 2; mt++) {
            const int r0r = cx.wM * 32 + cx.g + mt * 16, r8r = r0r + 8;
            const int ia0 = min(mbase + r0r, M - 1);
            const int ia8 = min(mbase + r8r, M - 1);
            const float d0 = (float)g_cnt[ia0];
            const float d8 = (float)g_cnt[ia8];
            #pragma unroll
            for (int jn = 0; jn < 8; jn++) {
                int col0 = cx.wN * 64 + jn * 8 + 2 * cx.t;
                float2 ra = *(const float2*)(g_R + (size_t)ia0 * H + col0);
                float2 rb = *(const float2*)(g_R + (size_t)ia8 * H + col0);
                float vb0 = sVb[col0], vb1 = sVb[col0 + 1];
                uint32_t u0 = cvt_tf32(fmaxf(acc[mt][jn][0] + ra.x + d0 * vb0, 0.f));
                uint32_t u1 = cvt_tf32(fmaxf(acc[mt][jn][1] + ra.y + d0 * vb1, 0.f));
                uint32_t u2 = cvt_tf32(fmaxf(acc[mt][jn][2] + rb.x + d8 * vb0, 0.f));
                uint32_t u3 = cvt_tf32(fmaxf(acc[mt][jn][3] + rb.y + d8 * vb1, 0.f));
                int slab = col0 >> 5, kk = col0 & 31;
                uint32_t* dst = (uint32_t*)(sHid + slab * 4096);
                *(uint2*)(dst + r0r * 32 + (kk ^ axor)) = make_uint2(u0, u1);
                *(uint2*)(dst + r8r * 32 + (kk ^ axor)) = make_uint2(u2, u3);
                acc[mt][jn][0] = acc[mt][jn][1] = acc[mt][jn][2] = acc[mt][jn][3] = 0.f;
            }
        }
        __syncthreads();

        #pragma unroll
        for (int ks16 = 0; ks16 < 16; ks16++)
            kstep<false>(cx, acc,
                         hidU + (uint32_t)((ks16 >> 2) * 16384),
                         w2U  + (uint32_t)((ks16 >> 2) * 16384), ks16 & 3);

        #pragma unroll
        for (int mt = 0; mt < 2; mt++) {
            const int r0r = cx.wM * 32 + cx.g + mt * 16, r8r = r0r + 8;
            #pragma unroll
            for (int jn = 0; jn < 8; jn++) {
                int col0 = cx.wN * 64 + jn * 8 + 2 * cx.t;
                float b0 = sB2[col0], b1 = sB2[col0 + 1];
                if (mbase + r0r < M)
                    *(float2*)(outp + (size_t)(mbase + r0r) * H + col0) =
                        make_float2(acc[mt][jn][0] + b0, acc[mt][jn][1] + b1);
                if (mbase + r8r < M)
                    *(float2*)(outp + (size_t)(mbase + r8r) * H + col0) =
                        make_float2(acc[mt][jn][2] + b0, acc[mt][jn][3] + b1);
            }
        }
    }
}

// ---------------------------------------------------------------------------
#define DYN_PRE  (24576 * 4)   //  96KB
#define DYN_EDGE (24576 * 4)   //  96KB
#define DYN_NODE (57344 * 4)   // 224KB

extern "C" void kernel_launch(void* const* d_in, const int* in_sizes, int n_in,
                              void* d_out, int out_size) {
    const float* x     = (const float*)d_in[0];
    const void*  eidx  = d_in[1];
    const float* eattr = (const float*)d_in[2];
    const float* We1   = (const float*)d_in[3];
    const float* be1   = (const float*)d_in[4];
    const float* We2   = (const float*)d_in[5];
    const float* be2   = (const float*)d_in[6];
    const float* Wn1   = (const float*)d_in[7];
    const float* bn1   = (const float*)d_in[8];
    const float* Wn2   = (const float*)d_in[9];
    const float* bn2   = (const float*)d_in[10];
    float* out = (float*)d_out;

    const int N = in_sizes[0] / H;
    const int E = in_sizes[1] / 2;

    cudaFuncSetAttribute(precompute_kernel, cudaFuncAttributeMaxDynamicSharedMemorySize, DYN_PRE);
    cudaFuncSetAttribute(edge_kernel,       cudaFuncAttributeMaxDynamicSharedMemorySize, DYN_EDGE);
    cudaFuncSetAttribute(node_kernel,       cudaFuncAttributeMaxDynamicSharedMemorySize, DYN_NODE);

    const int n4 = N * H / 4;
    int sgrid = (n4 + 255) / 256;
    const int need = 384 + (E + 255) / 256;
    if (sgrid < need) sgrid = need;

    // Launch order (4th launch gets the ncu capture -> edge_kernel):
    // 1:detect+zero 2:setup(zero/images/wcomb/hist) 3:precompute 4:edge 5:node
    detect_zero_kernel<<<(NCNT / 4 + 255) / 256, 256>>>((const unsigned int*)eidx);
    setup_kernel<<<sgrid, 256>>>(We1, We2, Wn1, Wn2, be2, eidx, n4, E);
    precompute_kernel<<<304, 256, DYN_PRE>>>(x, be1, bn1, N);
    edge_kernel<<<304, 256, DYN_EDGE>>>(eattr, eidx, E);
    node_kernel<<<152, 256, DYN_NODE>>>(bn2, out, N);
}

// round 16
// speedup vs baseline: 1.1080x; 1.0264x over previous
#include <cuda_runtime.h>
#include <cstdint>

#define H     128
#define MAX_N 50000
#define MAX_E 800000
#define NPAD  50048
#define NCNT  50176

// ---------------------------------------------------------------------------
// Scratch (device globals: no allocations allowed)
// ---------------------------------------------------------------------------
__device__ float g_agg[NPAD * H];          // Hsum (scatter target)
__device__ float g_Pa[NPAD * H];           // x @ Wa + be1
__device__ float g_Pb[NPAD * H];           // x @ Wb
__device__ int   g_cnt[NCNT];              // in-degree histogram
// tf32 weight images, n-major + granule swizzle for ldmatrix (4 chunks x 4096 floats)
__device__ float g_Wa[16384], g_Wb[16384], g_Wc[16384];
__device__ float g_Wn1t[16384], g_Wn2img[16384];
__device__ float g_Wcomb[16384];           // (We2 @ Wn1_bot) image
__device__ float g_vb[H];                  // be2 @ Wn1_bot
__device__ int   g_is64;

// ---------------------------------------------------------------------------
// helpers
// ---------------------------------------------------------------------------
__device__ __forceinline__ uint32_t smem_u32(const void* p) {
    uint32_t a;
    asm("{ .reg .u64 t; cvta.to.shared.u64 t, %1; cvt.u32.u64 %0, t; }" : "=r"(a) : "l"(p));
    return a;
}
__device__ __forceinline__ void cp16(uint32_t dst, const void* src, uint32_t sz) {
    asm volatile("cp.async.ca.shared.global [%0], [%1], 16, %2;"
                 :: "r"(dst), "l"(src), "r"(sz) : "memory");
}
__device__ __forceinline__ void cp16h(uint32_t dst, const void* src, uint32_t sz, uint64_t pol) {
    asm volatile("cp.async.ca.shared.global.L2::cache_hint [%0], [%1], 16, %2, %3;"
                 :: "r"(dst), "l"(src), "r"(sz), "l"(pol) : "memory");
}
#define CP_COMMIT() asm volatile("cp.async.commit_group;" ::: "memory")
#define CP_WAIT(n)  asm volatile("cp.async.wait_group %0;" :: "n"(n) : "memory")

__device__ __forceinline__ uint32_t cvt_tf32(float v) {
    uint32_t r; asm("cvt.rna.tf32.f32 %0, %1;" : "=r"(r) : "f"(v)); return r;
}
__device__ __forceinline__ void mma8(float* c, const uint32_t* a, const uint32_t* b) {
    asm volatile("mma.sync.aligned.m16n8k8.row.col.f32.tf32.tf32.f32 "
        "{%0,%1,%2,%3},{%4,%5,%6,%7},{%8,%9},{%0,%1,%2,%3};"
        : "+f"(c[0]), "+f"(c[1]), "+f"(c[2]), "+f"(c[3])
        : "r"(a[0]), "r"(a[1]), "r"(a[2]), "r"(a[3]), "r"(b[0]), "r"(b[1]));
}
__device__ __forceinline__ void ldmx4(uint32_t* r, uint32_t addr) {
    asm volatile("ldmatrix.sync.aligned.m8n8.x4.shared.b16 {%0,%1,%2,%3}, [%4];"
        : "=r"(r[0]), "=r"(r[1]), "=r"(r[2]), "=r"(r[3]) : "r"(addr));
}
__device__ __forceinline__ void red4h(float* p, float a, float b, float c, float d, uint64_t pol) {
    asm volatile("red.global.L2::cache_hint.add.v4.f32 [%0], {%1, %2, %3, %4}, %5;"
                 :: "l"(p), "f"(a), "f"(b), "f"(c), "f"(d), "l"(pol) : "memory");
}
__device__ __forceinline__ uint64_t policy_evict_last() {
    uint64_t pol;
    asm("createpolicy.fractional.L2::evict_last.b64 %0, 1.0;" : "=l"(pol));
    return pol;
}
__device__ __forceinline__ uint64_t policy_evict_first() {
    uint64_t pol;
    asm("createpolicy.fractional.L2::evict_first.b64 %0, 1.0;" : "=l"(pol));
    return pol;
}
__device__ __forceinline__ float4 ldg_el(const float* p, uint64_t pol) {
    float4 v;
    asm volatile("ld.global.L2::cache_hint.v4.f32 {%0,%1,%2,%3}, [%4], %5;"
                 : "=f"(v.x), "=f"(v.y), "=f"(v.z), "=f"(v.w) : "l"(p), "l"(pol));
    return v;
}

// ---------------------------------------------------------------------------
// launch 1: detect idx dtype + zero g_cnt
// ---------------------------------------------------------------------------
__global__ void detect_zero_kernel(const unsigned int* __restrict__ e) {
    int i = blockIdx.x * blockDim.x + threadIdx.x;
    if (i == 0)
        g_is64 = (e[1] == 0u && e[3] == 0u && e[5] == 0u && e[7] == 0u) ? 1 : 0;
    if (i < NCNT / 4) ((int4*)g_cnt)[i] = make_int4(0, 0, 0, 0);
}

// ---------------------------------------------------------------------------
// launch 2 (merged): zero agg + build 5 images + wcomb/vb + hist
// blocks [0,320): images; [320,384): wcomb; [384,...): hist
// image layout: W[row_off + c*32 + kk][n] at uint index
//   c*4096 + n*32 + (((kk>>2)^(n&7))<<2) + (kk&3), tf32(rna) pre-rounded.
// ---------------------------------------------------------------------------
__global__ void setup_kernel(const float* __restrict__ We1, const float* __restrict__ We2,
                             const float* __restrict__ Wn1, const float* __restrict__ Wn2,
                             const float* __restrict__ be2, const void* __restrict__ eidx,
                             int n4, int E) {
    int i = blockIdx.x * blockDim.x + threadIdx.x;
    if (i < n4) ((float4*)g_agg)[i] = make_float4(0.f, 0.f, 0.f, 0.f);
    const int b = blockIdx.x;
    if (b < 320) {
        int which = b >> 6;
        int idx = ((b & 63) << 8) + threadIdx.x;   // 0..16383
        const float* W; int row_off; float* img;
        switch (which) {
            case 0: W = We1; row_off =   0; img = g_Wa;   break;
            case 1: W = We1; row_off = 128; img = g_Wb;   break;
            case 2: W = We1; row_off = 256; img = g_Wc;   break;
            case 3: W = Wn1; row_off =   0; img = g_Wn1t; break;
            default: W = Wn2; row_off =  0; img = g_Wn2img; break;
        }
        int c = idx >> 12, rem = idx & 4095, kk = rem >> 7, n = rem & 127;
        float v = W[(size_t)(row_off + c * 32 + kk) * H + n];
        ((uint32_t*)img)[c * 4096 + n * 32 + (((kk >> 2) ^ (n & 7)) << 2) + (kk & 3)] = cvt_tf32(v);
    } else if (b < 384) {
        int idx = ((b - 320) << 8) + threadIdx.x;  // 0..16383
        int k = idx >> 7, n = idx & 127;
        float s = 0.f;
        for (int j = 0; j < H; j++) s += We2[k * H + j] * Wn1[(size_t)(128 + j) * H + n];
        int c = k >> 5, kk = k & 31;
        ((uint32_t*)g_Wcomb)[c * 4096 + n * 32 + (((kk >> 2) ^ (n & 7)) << 2) + (kk & 3)] = cvt_tf32(s);
        if (idx < H) {
            float sv = 0.f;
            for (int j = 0; j < H; j++) sv += be2[j] * Wn1[(size_t)(128 + j) * H + idx];
            g_vb[idx] = sv;
        }
    } else {
        int e = ((b - 384) << 8) + threadIdx.x;
        if (e < E) {
            int col = g_is64 ? (int)((const long long*)eidx)[(long long)E + e]
                             : ((const int*)eidx)[E + e];
            atomicAdd(&g_cnt[col], 1);
        }
    }
}

// ===========================================================================
// Tile machinery: 128x128 tile, 8 warps (4M x 2N), tf32 mma.sync + ldmatrix
// ===========================================================================
struct TileCtx {
    int lane, g, t, wM, wN, ar, halfA, l7;
    uint32_t khA, khB, aRow0, aRow1, bRow0, bRow1, bRow2, bRow3;
    __device__ __forceinline__ void init(int tid) {
        lane = tid & 31;
        int warp = tid >> 5;
        g = lane >> 2; t = lane & 3;
        wM = warp & 3; wN = warp >> 2;
        ar = tid >> 1; halfA = tid & 1;
        l7 = lane & 7;
        khA = (uint32_t)(lane >> 4);
        khB = (uint32_t)((lane >> 3) & 1);
        aRow0 = (uint32_t)((wM * 32 + ((lane >> 3) & 1) * 8 + l7) * 128);
        aRow1 = aRow0 + 16 * 128;
        uint32_t jo = (uint32_t)(lane >> 4);
        bRow0 = (uint32_t)((wN * 64 + (0 + jo) * 8 + l7) * 128);
        bRow1 = (uint32_t)((wN * 64 + (2 + jo) * 8 + l7) * 128);
        bRow2 = (uint32_t)((wN * 64 + (4 + jo) * 8 + l7) * 128);
        bRow3 = (uint32_t)((wN * 64 + (6 + jo) * 8 + l7) * 128);
    }
};

template<bool DOCVT>
__device__ __forceinline__ void kstep(const TileCtx& cx, float acc[2][8][4],
                                      uint32_t Ab, uint32_t Bb, int ks) {
    uint32_t gA = (uint32_t)(((2 * ks + cx.khA) ^ cx.l7) << 4);
    uint32_t gB = (uint32_t)(((2 * ks + cx.khB) ^ cx.l7) << 4);
    uint32_t a0[4], a1[4];
    ldmx4(a0, Ab + cx.aRow0 + gA);
    ldmx4(a1, Ab + cx.aRow1 + gA);
    if (DOCVT) {
        #pragma unroll
        for (int i = 0; i < 4; i++) {
            a0[i] = cvt_tf32(__uint_as_float(a0[i]));
            a1[i] = cvt_tf32(__uint_as_float(a1[i]));
        }
    }
    uint32_t bf[16];
    ldmx4(bf + 0,  Bb + cx.bRow0 + gB);
    ldmx4(bf + 4,  Bb + cx.bRow1 + gB);
    ldmx4(bf + 8,  Bb + cx.bRow2 + gB);
    ldmx4(bf + 12, Bb + cx.bRow3 + gB);
    #pragma unroll
    for (int jn = 0; jn < 8; jn++) {
        mma8(acc[0][jn], a0, bf + 2 * jn);
        mma8(acc[1][jn], a1, bf + 2 * jn);
    }
}

// ---------------------------------------------------------------------------
// Fused precompute (2 passes): Pa = x@Wa + be1, Pb = x@Wb
// smem floats: A full tile 16384 | B dbuf 2x4096 = 24576 (96KB) -> 2 CTA/SM
// ---------------------------------------------------------------------------
__global__ void __launch_bounds__(256, 2)
precompute_kernel(const float* __restrict__ x, const float* __restrict__ be1, int M)
{
    extern __shared__ __align__(16) float sm[];
    __shared__ float sB1[128];
    const int tid = threadIdx.x;
    TileCtx cx; cx.init(tid);
    const uint32_t aBufU = smem_u32(sm);
    const uint32_t bBufU = smem_u32(sm + 16384);
    if (tid < 128) sB1[tid] = be1[tid];

    const int T = (M + 127) >> 7;
    for (int tile = blockIdx.x; tile < T; tile += gridDim.x) {
        const int mbase = tile << 7;
        __syncthreads();

        auto stageA = [&](int c) {
            bool valid = (mbase + cx.ar) < M;
            const float* srcA = x + (size_t)(valid ? (mbase + cx.ar) : 0) * H
                              + (c << 5) + cx.halfA * 16;
            uint32_t dstA = aBufU + (uint32_t)(c * 16384 + cx.ar * 128);
            uint32_t sz = valid ? 16u : 0u;
            #pragma unroll
            for (int i = 0; i < 4; i++) {
                int q = cx.halfA * 4 + i, qs = q ^ (cx.ar & 7);
                cp16(dstA + qs * 16, srcA + i * 4, sz);
            }
        };
        auto stageB = [&](int s) {
            const float* img = ((s >> 2) == 0) ? g_Wa : g_Wb;
            const float4* srcB = (const float4*)(img + (s & 3) * 4096) + tid;
            uint32_t dstB = bBufU + (uint32_t)((s & 1) * 16384) + (uint32_t)tid * 16;
            #pragma unroll
            for (int i = 0; i < 4; i++) cp16(dstB + i * 4096, srcB + i * 256, 16);
        };

        float acc[2][8][4];
        #pragma unroll
        for (int mt = 0; mt < 2; mt++)
            #pragma unroll
            for (int jn = 0; jn < 8; jn++)
                #pragma unroll
                for (int i = 0; i < 4; i++) acc[mt][jn][i] = 0.f;

        stageA(0); stageB(0); CP_COMMIT();
        stageA(1); stageB(1); CP_COMMIT();

        for (int s = 0; s < 8; s++) {
            if (s < 7) { CP_WAIT(1); } else { CP_WAIT(0); }
            __syncthreads();
            uint32_t Ab = aBufU + (uint32_t)((s & 3) * 16384);
            uint32_t Bb = bBufU + (uint32_t)((s & 1) * 16384);
            #pragma unroll
            for (int ks = 0; ks < 4; ks++) kstep<true>(cx, acc, Ab, Bb, ks);
            __syncthreads();
            int ns = s + 2;
            if (ns < 8) {
                if (ns < 4) stageA(ns);
                stageB(ns);
                CP_COMMIT();
            }
            if ((s & 3) == 3) {
                int pass = s >> 2;
                float* outp = (pass == 0) ? g_Pa : g_Pb;
                #pragma unroll
                for (int mt = 0; mt < 2; mt++) {
                    const int r0r = cx.wM * 32 + cx.g + mt * 16, r8r = r0r + 8;
                    #pragma unroll
                    for (int jn = 0; jn < 8; jn++) {
                        int col0 = cx.wN * 64 + jn * 8 + 2 * cx.t;
                        float b0 = 0.f, b1 = 0.f;
                        if (pass == 0) { b0 = sB1[col0]; b1 = sB1[col0 + 1]; }
                        if (mbase + r0r < M)
                            *(float2*)(outp + (size_t)(mbase + r0r) * H + col0) =
                                make_float2(acc[mt][jn][0] + b0, acc[mt][jn][1] + b1);
                        if (mbase + r8r < M)
                            *(float2*)(outp + (size_t)(mbase + r8r) * H + col0) =
                                make_float2(acc[mt][jn][2] + b0, acc[mt][jn][3] + b1);
                        acc[mt][jn][0] = acc[mt][jn][1] = 0.f;
                        acc[mt][jn][2] = acc[mt][jn][3] = 0.f;
                    }
                }
            }
        }
    }
}

// ---------------------------------------------------------------------------
// Edge kernel (unchanged from R15 winner): Q = eattr@Wc (Wc persistent);
// hid = relu(Q + Pa[row] + Pb[col]); coalesced epilogue via 64-slot SMEM
// transpose; red.v4 evict_last; Pa/Pb evict_last; eattr evict_first.
// smem floats: A dbuf 8192 (reused as transpose buf) | sW1 16384 = 96KB
// ---------------------------------------------------------------------------
__global__ void __launch_bounds__(256, 2)
edge_kernel(const float* __restrict__ eattr, const void* __restrict__ eidx, int M)
{
    extern __shared__ __align__(16) float sm[];
    float* const sW1 = sm + 8192;
    __shared__ int sRow[2][128], sCol[2][128];

    const int tid = threadIdx.x;
    const int warp = tid >> 5;
    TileCtx cx; cx.init(tid);
    const uint32_t aBufU = smem_u32(sm);
    const uint32_t w1U   = smem_u32(sW1);
    const int is64v = g_is64;
    const int ntiles = (M + 127) >> 7;
    const uint64_t polL = policy_evict_last();
    const uint64_t polF = policy_evict_first();

    auto load_idx = [&](int t, int b) {
        if (tid < 128) {
            int rI = 0, cI = 0;
            int e = (t << 7) + tid;
            if (t < ntiles && e < M) {
                if (is64v) {
                    const long long* p = (const long long*)eidx;
                    rI = (int)p[e]; cI = (int)p[(long long)M + e];
                } else {
                    const int* p = (const int*)eidx;
                    rI = p[e]; cI = p[M + e];
                }
            }
            sRow[b][tid] = rI; sCol[b][tid] = cI;
        }
    };

    { // persistent Wc image
        const float4* s1 = (const float4*)g_Wc;
        float4* d1 = (float4*)sW1;
        #pragma unroll
        for (int i = 0; i < 16; i++) d1[tid + i * 256] = s1[tid + i * 256];
    }
    load_idx(blockIdx.x, 0);
    __syncthreads();

    auto stage = [&](int mbase, int c) {
        bool valid = (mbase + cx.ar) < M;
        const float* srcA = eattr + (size_t)(valid ? (mbase + cx.ar) : 0) * H
                          + (c << 5) + cx.halfA * 16;
        uint32_t dstA = aBufU + (uint32_t)((c & 1) * 16384 + cx.ar * 128);
        uint32_t sz = valid ? 16u : 0u;
        #pragma unroll
        for (int i = 0; i < 4; i++) {
            int q = cx.halfA * 4 + i, qs = q ^ (cx.ar & 7);
            cp16h(dstA + qs * 16, srcA + i * 4, sz, polF);
        }
        CP_COMMIT();
    };

    int it = 0;
    for (int tile = blockIdx.x; tile < ntiles; tile += gridDim.x, it ^= 1) {
        const int mbase = tile << 7;
        load_idx(tile + gridDim.x, it ^ 1);

        float acc[2][8][4];
        #pragma unroll
        for (int mt = 0; mt < 2; mt++)
            #pragma unroll
            for (int jn = 0; jn < 8; jn++)
                #pragma unroll
                for (int i = 0; i < 4; i++) acc[mt][jn][i] = 0.f;

        stage(mbase, 0); stage(mbase, 1);
        #pragma unroll
        for (int c = 0; c < 4; c++) {
            if (c < 3) { CP_WAIT(1); } else { CP_WAIT(0); }
            __syncthreads();
            uint32_t Ab = aBufU + (uint32_t)((c & 1) * 16384);
            uint32_t Bb = w1U + (uint32_t)(c * 16384);
            #pragma unroll
            for (int ks = 0; ks < 4; ks++) kstep<true>(cx, acc, Ab, Bb, ks);
            __syncthreads();
            if (c + 2 < 4) stage(mbase, c + 2);
        }

        // ---- epilogue: transpose acc via SMEM, coalesced gather/scatter ----
        #pragma unroll
        for (int mt = 0; mt < 2; mt++) {
            const int slotA = cx.wM * 16 + cx.g;
            const int slotB = slotA + 8;
            #pragma unroll
            for (int jn = 0; jn < 8; jn++) {
                int col0 = cx.wN * 64 + jn * 8 + 2 * cx.t;
                int ca = col0 ^ ((slotA & 7) << 2);
                int cb = col0 ^ ((slotB & 7) << 2);
                *(float2*)(sm + slotA * 128 + ca) = make_float2(acc[mt][jn][0], acc[mt][jn][1]);
                *(float2*)(sm + slotB * 128 + cb) = make_float2(acc[mt][jn][2], acc[mt][jn][3]);
            }
            __syncthreads();
            #pragma unroll
            for (int ss = 0; ss < 8; ss++) {
                const int slot = warp * 8 + ss;
                const int row  = (slot >> 4) * 32 + mt * 16 + (slot & 15);
                const bool valid = (mbase + row) < M;
                const int ridx = sRow[it][row], cidx = sCol[it][row];
                const int lc = cx.lane << 2;
                float4 q = *(const float4*)(sm + slot * 128
                                            + ((cx.lane ^ (slot & 7)) << 2));
                if (valid) {
                    const float4 pa = ldg_el(g_Pa + (size_t)ridx * H + lc, polL);
                    const float4 pb = ldg_el(g_Pb + (size_t)cidx * H + lc, polL);
                    red4h(g_agg + (size_t)cidx * H + lc,
                          fmaxf(q.x + pa.x + pb.x, 0.f),
                          fmaxf(q.y + pa.y + pb.y, 0.f),
                          fmaxf(q.z + pa.z + pb.z, 0.f),
                          fmaxf(q.w + pa.w + pb.w, 0.f), polL);
                }
            }
            __syncthreads();
        }
    }
}

// ---------------------------------------------------------------------------
// Node kernel (K=256 fused): hid = relu([Hsum | x] @ [Wcomb; Wn1t]
//                                        + cnt[m]*vb + bn1);
// out = hid@Wn2 + bn2.   (R pass + buffer eliminated algebraically.)
// smem floats: A dbuf 8192 | B dbuf 8192 | sW2 16384 | sHid 16384 = 49152 (192KB)
// ---------------------------------------------------------------------------
__global__ void __launch_bounds__(256, 1)
node_kernel(const float* __restrict__ x, const float* __restrict__ b1v,
            const float* __restrict__ b2v, float* __restrict__ outp, int M)
{
    extern __shared__ __align__(16) float sm[];
    float* const sBb  = sm + 8192;
    float* const sW2  = sm + 16384;
    float* const sHid = sm + 32768;
    __shared__ float sB1[128], sB2[128], sVb[128];

    const int tid = threadIdx.x;
    TileCtx cx; cx.init(tid);
    const uint32_t aBufU = smem_u32(sm);
    const uint32_t bBufU = smem_u32(sBb);
    const uint32_t w2U   = smem_u32(sW2);
    const uint32_t hidU  = smem_u32(sHid);

    { // persistent Wn2 image
        const float4* s2 = (const float4*)g_Wn2img;
        float4* d2 = (float4*)sW2;
        #pragma unroll
        for (int i = 0; i < 16; i++) d2[tid + i * 256] = s2[tid + i * 256];
    }
    if (tid < 128) { sB1[tid] = b1v[tid]; sB2[tid] = b2v[tid]; sVb[tid] = g_vb[tid]; }
    __syncthreads();

    const int ntiles = (M + 127) >> 7;
    for (int tile = blockIdx.x; tile < ntiles; tile += gridDim.x) {
        const int mbase = tile << 7;
        __syncthreads();

        // A chunk c: c<4 -> Hsum(g_agg) cols c*32; c>=4 -> x cols (c-4)*32
        auto stage = [&](int c) {
            bool valid = (mbase + cx.ar) < M;
            const float* srcbase = (c < 4) ? g_agg : x;
            const float* srcA = srcbase + (size_t)(valid ? (mbase + cx.ar) : 0) * H
                              + ((c & 3) << 5) + cx.halfA * 16;
            uint32_t dstA = aBufU + (uint32_t)((c & 1) * 16384 + cx.ar * 128);
            uint32_t sz = valid ? 16u : 0u;
            #pragma unroll
            for (int i = 0; i < 4; i++) {
                int q = cx.halfA * 4 + i, qs = q ^ (cx.ar & 7);
                cp16(dstA + qs * 16, srcA + i * 4, sz);
            }
            const float* img = (c < 4) ? g_Wcomb : g_Wn1t;
            const float4* srcB = (const float4*)(img + (c & 3) * 4096) + tid;
            uint32_t dstB = bBufU + (uint32_t)((c & 1) * 16384) + (uint32_t)tid * 16;
            #pragma unroll
            for (int i = 0; i < 4; i++) cp16(dstB + i * 4096, srcB + i * 256, 16);
            CP_COMMIT();
        };

        float acc[2][8][4];
        #pragma unroll
        for (int mt = 0; mt < 2; mt++)
            #pragma unroll
            for (int jn = 0; jn < 8; jn++)
                #pragma unroll
                for (int i = 0; i < 4; i++) acc[mt][jn][i] = 0.f;

        stage(0); stage(1);
        // ---------------- L1: K=256 (8 chunks), double-buffered -------------
        #pragma unroll
        for (int c = 0; c < 8; c++) {
            if (c < 7) { CP_WAIT(1); } else { CP_WAIT(0); }
            __syncthreads();
            uint32_t Ab = aBufU + (uint32_t)((c & 1) * 16384);
            uint32_t Bb = bBufU + (uint32_t)((c & 1) * 16384);
            #pragma unroll
            for (int ks = 0; ks < 4; ks++) kstep<true>(cx, acc, Ab, Bb, ks);
            __syncthreads();
            if (c + 2 < 8) stage(c + 2);
        }

        // hid = relu(acc + cnt[m]*vb + bn1) -> sHid (tf32, A layout)
        const int axor = cx.g << 2;
        #pragma unroll
        for (int mt = 0; mt < 2; mt++) {
            const int r0r = cx.wM * 32 + cx.g + mt * 16, r8r = r0r + 8;
            const int ia0 = min(mbase + r0r, M - 1);
            const int ia8 = min(mbase + r8r, M - 1);
            const float d0 = (float)g_cnt[ia0];
            const float d8 = (float)g_cnt[ia8];
            #pragma unroll
            for (int jn = 0; jn < 8; jn++) {
                int col0 = cx.wN * 64 + jn * 8 + 2 * cx.t;
                float vb0 = sVb[col0], vb1 = sVb[col0 + 1];
                float bn0 = sB1[col0], bn1v = sB1[col0 + 1];
                uint32_t u0 = cvt_tf32(fmaxf(acc[mt][jn][0] + d0 * vb0 + bn0, 0.f));
                uint32_t u1 = cvt_tf32(fmaxf(acc[mt][jn][1] + d0 * vb1 + bn1v, 0.f));
                uint32_t u2 = cvt_tf32(fmaxf(acc[mt][jn][2] + d8 * vb0 + bn0, 0.f));
                uint32_t u3 = cvt_tf32(fmaxf(acc[mt][jn][3] + d8 * vb1 + bn1v, 0.f));
                int slab = col0 >> 5, kk = col0 & 31;
                uint32_t* dst = (uint32_t*)(sHid + slab * 4096);
                *(uint2*)(dst + r0r * 32 + (kk ^ axor)) = make_uint2(u0, u1);
                *(uint2*)(dst + r8r * 32 + (kk ^ axor)) = make_uint2(u2, u3);
                acc[mt][jn][0] = acc[mt][jn][1] = acc[mt][jn][2] = acc[mt][jn][3] = 0.f;
            }
        }
        __syncthreads();

        // ------------------------- L2 (K=128) ------------------------------
        #pragma unroll
        for (int ks16 = 0; ks16 < 16; ks16++)
            kstep<false>(cx, acc,
                         hidU + (uint32_t)((ks16 >> 2) * 16384),
                         w2U  + (uint32_t)((ks16 >> 2) * 16384), ks16 & 3);

        #pragma unroll
        for (int mt = 0; mt < 2; mt++) {
            const int r0r = cx.wM * 32 + cx.g + mt * 16, r8r = r0r + 8;
            #pragma unroll
            for (int jn = 0; jn < 8; jn++) {
                int col0 = cx.wN * 64 + jn * 8 + 2 * cx.t;
                float b0 = sB2[col0], b1 = sB2[col0 + 1];
                if (mbase + r0r < M)
                    *(float2*)(outp + (size_t)(mbase + r0r) * H + col0) =
                        make_float2(acc[mt][jn][0] + b0, acc[mt][jn][1] + b1);
                if (mbase + r8r < M)
                    *(float2*)(outp + (size_t)(mbase + r8r) * H + col0) =
                        make_float2(acc[mt][jn][2] + b0, acc[mt][jn][3] + b1);
            }
        }
    }
}

// ---------------------------------------------------------------------------
#define DYN_PRE  (24576 * 4)   //  96KB
#define DYN_EDGE (24576 * 4)   //  96KB
#define DYN_NODE (49152 * 4)   // 192KB

extern "C" void kernel_launch(void* const* d_in, const int* in_sizes, int n_in,
                              void* d_out, int out_size) {
    const float* x     = (const float*)d_in[0];
    const void*  eidx  = d_in[1];
    const float* eattr = (const float*)d_in[2];
    const float* We1   = (const float*)d_in[3];
    const float* be1   = (const float*)d_in[4];
    const float* We2   = (const float*)d_in[5];
    const float* be2   = (const float*)d_in[6];
    const float* Wn1   = (const float*)d_in[7];
    const float* bn1   = (const float*)d_in[8];
    const float* Wn2   = (const float*)d_in[9];
    const float* bn2   = (const float*)d_in[10];
    float* out = (float*)d_out;

    const int N = in_sizes[0] / H;
    const int E = in_sizes[1] / 2;

    cudaFuncSetAttribute(precompute_kernel, cudaFuncAttributeMaxDynamicSharedMemorySize, DYN_PRE);
    cudaFuncSetAttribute(edge_kernel,       cudaFuncAttributeMaxDynamicSharedMemorySize, DYN_EDGE);
    cudaFuncSetAttribute(node_kernel,       cudaFuncAttributeMaxDynamicSharedMemorySize, DYN_NODE);

    const int n4 = N * H / 4;
    int sgrid = (n4 + 255) / 256;
    const int need = 384 + (E + 255) / 256;
    if (sgrid < need) sgrid = need;

    // Launch order (4th launch gets the ncu capture -> edge_kernel):
    // 1:detect+zero 2:setup(zero/images/wcomb/hist) 3:precompute 4:edge 5:node
    detect_zero_kernel<<<(NCNT / 4 + 255) / 256, 256>>>((const unsigned int*)eidx);
    setup_kernel<<<sgrid, 256>>>(We1, We2, Wn1, Wn2, be2, eidx, n4, E);
    precompute_kernel<<<304, 256, DYN_PRE>>>(x, be1, N);
    edge_kernel<<<304, 256, DYN_EDGE>>>(eattr, eidx, E);
    node_kernel<<<152, 256, DYN_NODE>>>(x, bn1, bn2, out, N);
}